// round 1
// baseline (speedup 1.0000x reference)
#include <cuda_runtime.h>

#define BATCH 16384
#define NEG 5
#define WARPS_PER_BLOCK 8
#define THREADS (WARPS_PER_BLOCK * 32)
#define NBLOCKS (BATCH / WARPS_PER_BLOCK)   // 2048

__device__ float g_partials[NBLOCKS];

__device__ __forceinline__ float logsig(float x) {
    // stable log(sigmoid(x)) = min(x,0) - log1p(exp(-|x|))
    return fminf(x, 0.0f) - log1pf(expf(-fabsf(x)));
}

__global__ void __launch_bounds__(THREADS)
sg_main(const float* __restrict__ emb,
        const int* __restrict__ centers,
        const int* __restrict__ contexts,
        const int* __restrict__ negs) {
    const int lane = threadIdx.x & 31;
    const int warp = threadIdx.x >> 5;
    const int b = blockIdx.x * WARPS_PER_BLOCK + warp;   // batch element

    // Row = 128 floats = 32 float4; lane i takes float4 i -> 512B coalesced.
    const float4* e4 = reinterpret_cast<const float4*>(emb);

    // Gather all indices first so the 7 row loads can be issued back-to-back (MLP=7).
    const int ic = centers[b];
    const int it = contexts[b];
    const int in0 = negs[b * NEG + 0];
    const int in1 = negs[b * NEG + 1];
    const int in2 = negs[b * NEG + 2];
    const int in3 = negs[b * NEG + 3];
    const int in4 = negs[b * NEG + 4];

    const float4 u  = e4[(size_t)ic  * 32 + lane];
    const float4 v  = e4[(size_t)it  * 32 + lane];
    const float4 w0 = e4[(size_t)in0 * 32 + lane];
    const float4 w1 = e4[(size_t)in1 * 32 + lane];
    const float4 w2 = e4[(size_t)in2 * 32 + lane];
    const float4 w3 = e4[(size_t)in3 * 32 + lane];
    const float4 w4 = e4[(size_t)in4 * 32 + lane];

    // sum_k (u . nv_k) == u . (sum_k nv_k)
    float4 ns;
    ns.x = w0.x + w1.x + w2.x + w3.x + w4.x;
    ns.y = w0.y + w1.y + w2.y + w3.y + w4.y;
    ns.z = w0.z + w1.z + w2.z + w3.z + w4.z;
    ns.w = w0.w + w1.w + w2.w + w3.w + w4.w;

    float pos = u.x * v.x  + u.y * v.y  + u.z * v.z  + u.w * v.w;
    float neg = u.x * ns.x + u.y * ns.y + u.z * ns.z + u.w * ns.w;

    #pragma unroll
    for (int o = 16; o > 0; o >>= 1) {
        pos += __shfl_xor_sync(0xffffffffu, pos, o);
        neg += __shfl_xor_sync(0xffffffffu, neg, o);
    }

    __shared__ float sm[WARPS_PER_BLOCK];
    if (lane == 0)
        sm[warp] = logsig(pos) + logsig(-neg);
    __syncthreads();

    if (threadIdx.x == 0) {
        float s = 0.0f;
        #pragma unroll
        for (int i = 0; i < WARPS_PER_BLOCK; i++) s += sm[i];
        g_partials[blockIdx.x] = s;
    }
}

__global__ void __launch_bounds__(256)
sg_reduce(float* __restrict__ out) {
    __shared__ float sm[256];
    float s = 0.0f;
    for (int i = threadIdx.x; i < NBLOCKS; i += 256)
        s += g_partials[i];
    sm[threadIdx.x] = s;
    __syncthreads();
    #pragma unroll
    for (int o = 128; o > 0; o >>= 1) {
        if (threadIdx.x < o) sm[threadIdx.x] += sm[threadIdx.x + o];
        __syncthreads();
    }
    if (threadIdx.x == 0) out[0] = -sm[0];
}

extern "C" void kernel_launch(void* const* d_in, const int* in_sizes, int n_in,
                              void* d_out, int out_size) {
    const float* emb      = (const float*)d_in[0];
    const int*   centers  = (const int*)  d_in[1];
    const int*   contexts = (const int*)  d_in[2];
    const int*   negs     = (const int*)  d_in[3];
    float*       out      = (float*)d_out;

    sg_main<<<NBLOCKS, THREADS>>>(emb, centers, contexts, negs);
    sg_reduce<<<1, 256>>>(out);
}